// round 2
// baseline (speedup 1.0000x reference)
#include <cuda_runtime.h>
#include <math.h>

// Problem constants
#define HW 4096           // 64*64
#define IMG_H 64
#define IMG_W 64

// ---------------- scratch (static device globals; no allocation) ----------------
__device__ float g_value_t[12u * 4096u * 256u];   // value conv out, token-major (12,4096,256)
__device__ float g_off    [4u * 192u * 4096u];    // offset conv out, NCHW
__device__ float g_attn   [4u * 96u  * 4096u];    // attn conv out, NCHW
__device__ float g_samp_t [4u * 4096u * 256u];    // MSDA out token-major
__device__ float g_samp   [4u * 256u * 4096u];    // MSDA out NCHW (for final conv)

// ---------------- generic 3x3 SAME conv, fp32 direct ----------------
// Block: 256 threads (16x16). Each block: 32x32 spatial tile x COUT_TILE out channels.
// Each thread: 2x2 pixels x COUT_TILE channels. Input staged in smem, 4 in-ch chunks.
// TMAJOR: store token-major out[(img*HW+pix)*cout_total + c] instead of NCHW.
template<int CIN, int COUT_TILE, bool TMAJOR>
__global__ __launch_bounds__(256, 2)
void conv3x3_kernel(const float* __restrict__ in, const float* __restrict__ wgt,
                    const float* __restrict__ bias, float* __restrict__ out,
                    int cout_total)
{
    constexpr int CCH = 4;
    __shared__ float s_in[CCH][34][35];          // pad to 35 -> conflict-free LDS
    __shared__ float s_w[COUT_TILE][CCH][9];

    const int tx = threadIdx.x, ty = threadIdx.y;
    const int tid = ty * 16 + tx;
    const int nco = cout_total / COUT_TILE;
    const int img = blockIdx.z / nco;
    const int co_base = (blockIdx.z % nco) * COUT_TILE;
    const int bx0 = blockIdx.x * 32, by0 = blockIdx.y * 32;

    const float* in_img = in + (size_t)img * CIN * HW;

    float acc[COUT_TILE][4];
    #pragma unroll
    for (int co = 0; co < COUT_TILE; co++)
        #pragma unroll
        for (int q = 0; q < 4; q++) acc[co][q] = 0.f;

    for (int cb = 0; cb < CIN; cb += CCH) {
        // stage input tile (with halo, zero padded)
        for (int i = tid; i < CCH * 34 * 34; i += 256) {
            int ci = i / (34 * 34); int r = i % (34 * 34);
            int iy = r / 34, ix = r % 34;
            int gy = by0 + iy - 1, gx = bx0 + ix - 1;
            float v = 0.f;
            if ((unsigned)gy < (unsigned)IMG_H && (unsigned)gx < (unsigned)IMG_W)
                v = in_img[((size_t)(cb + ci) * IMG_H + gy) * IMG_W + gx];
            s_in[ci][iy][ix] = v;
        }
        // stage weights
        for (int i = tid; i < COUT_TILE * CCH * 9; i += 256) {
            int co = i / (CCH * 9); int r2 = i % (CCH * 9);
            int ci = r2 / 9, k = r2 % 9;
            s_w[co][ci][k] = wgt[((size_t)(co_base + co) * CIN + cb + ci) * 9 + k];
        }
        __syncthreads();

        #pragma unroll
        for (int ci = 0; ci < CCH; ci++) {
            float win[4][4];
            #pragma unroll
            for (int r = 0; r < 4; r++)
                #pragma unroll
                for (int c2 = 0; c2 < 4; c2++)
                    win[r][c2] = s_in[ci][2 * ty + r][2 * tx + c2];
            #pragma unroll
            for (int co = 0; co < COUT_TILE; co++) {
                #pragma unroll
                for (int k = 0; k < 9; k++) {
                    const float wv = s_w[co][ci][k];
                    const int dy = k / 3, dx = k % 3;
                    acc[co][0] += wv * win[dy][dx];
                    acc[co][1] += wv * win[dy][dx + 1];
                    acc[co][2] += wv * win[dy + 1][dx];
                    acc[co][3] += wv * win[dy + 1][dx + 1];
                }
            }
        }
        __syncthreads();
    }

    const int oy = by0 + 2 * ty, ox = bx0 + 2 * tx;
    if (TMAJOR) {
        #pragma unroll
        for (int q = 0; q < 4; q++) {
            int py = oy + (q >> 1), px = ox + (q & 1);
            float* op = out + ((size_t)img * HW + py * IMG_W + px) * cout_total + co_base;
            #pragma unroll
            for (int co = 0; co < COUT_TILE; co++)
                op[co] = acc[co][q] + bias[co_base + co];
        }
    } else {
        #pragma unroll
        for (int co = 0; co < COUT_TILE; co++) {
            float bv = bias[co_base + co];
            float* op = out + (((size_t)img * cout_total + co_base + co) * IMG_H + oy) * IMG_W + ox;
            op[0]  = acc[co][0] + bv;
            op[1]  = acc[co][1] + bv;
            op[64] = acc[co][2] + bv;
            op[65] = acc[co][3] + bv;
        }
    }
}

// ---------------- tiled transpose: out[c][r] = in[r][c], per blockIdx.z matrix -------
__global__ void transpose_kernel(const float* __restrict__ in, float* __restrict__ out,
                                 int rows, int cols)
{
    __shared__ float tile[32][33];
    size_t base = (size_t)blockIdx.z * rows * cols;
    int c0 = blockIdx.x * 32, r0 = blockIdx.y * 32;
    int x = c0 + threadIdx.x;
    for (int j = threadIdx.y; j < 32; j += 8)
        tile[j][threadIdx.x] = in[base + (size_t)(r0 + j) * cols + x];
    __syncthreads();
    int x2 = r0 + threadIdx.x;
    for (int j = threadIdx.y; j < 32; j += 8)
        out[base + (size_t)(c0 + j) * rows + x2] = tile[threadIdx.x][j];
}

// ---------------- MSDA sampling + fused softmax -------------------------------------
// One warp per (b, pix, head); lane = channel d (0..31).
__global__ __launch_bounds__(256)
void msda_kernel(const float* __restrict__ value_t, const float* __restrict__ off,
                 const float* __restrict__ attn, const float* __restrict__ refp,
                 float* __restrict__ out_t)
{
    int gw = blockIdx.x * 8 + (threadIdx.x >> 5);   // (b*4096 + pix)*8 + head
    int lane = threadIdx.x & 31;
    int head = gw & 7;
    int pix  = (gw >> 3) & 4095;
    int b    = gw >> 15;

    // softmax over L*P = 12 logits (broadcast loads)
    float lg[12]; float mx = -1e30f;
    #pragma unroll
    for (int j = 0; j < 12; j++) {
        lg[j] = attn[((size_t)b * 96 + head * 12 + j) * HW + pix];
        mx = fmaxf(mx, lg[j]);
    }
    float den = 0.f;
    #pragma unroll
    for (int j = 0; j < 12; j++) { lg[j] = expf(lg[j] - mx); den += lg[j]; }
    float rden = 1.f / den;

    float acc = 0.f;
    #pragma unroll
    for (int l = 0; l < 3; l++) {
        float rx = refp[((size_t)(b * HW + pix) * 3 + l) * 2 + 0];
        float ry = refp[((size_t)(b * HW + pix) * 3 + l) * 2 + 1];
        const float* vb = value_t + ((size_t)(b * 3 + l) * HW) * 256 + head * 32 + lane;
        #pragma unroll
        for (int p = 0; p < 4; p++) {
            int ch = ((head * 3 + l) * 4 + p) * 2;
            float ox = off[((size_t)b * 192 + ch)     * HW + pix];
            float oy = off[((size_t)b * 192 + ch + 1) * HW + pix];
            float a = lg[l * 4 + p] * rden;
            // loc = ref + off/(W,H); x = loc_x*W - 0.5 = ref_x*64 + ox - 0.5
            float xf = rx * 64.f + ox - 0.5f;
            float yf = ry * 64.f + oy - 0.5f;
            float x0f = floorf(xf), y0f = floorf(yf);
            int x0 = (int)x0f, y0 = (int)y0f;
            float lx = xf - x0f, ly = yf - y0f;
            float w00 = (1.f - lx) * (1.f - ly) * a;
            float w10 = lx * (1.f - ly) * a;
            float w01 = (1.f - lx) * ly * a;
            float w11 = lx * ly * a;
            if ((unsigned)x0       < 64u && (unsigned)y0       < 64u) acc += w00 * vb[(size_t)(y0 * 64 + x0) * 256];
            if ((unsigned)(x0 + 1) < 64u && (unsigned)y0       < 64u) acc += w10 * vb[(size_t)(y0 * 64 + x0 + 1) * 256];
            if ((unsigned)x0       < 64u && (unsigned)(y0 + 1) < 64u) acc += w01 * vb[(size_t)((y0 + 1) * 64 + x0) * 256];
            if ((unsigned)(x0 + 1) < 64u && (unsigned)(y0 + 1) < 64u) acc += w11 * vb[(size_t)((y0 + 1) * 64 + x0 + 1) * 256];
        }
    }
    out_t[(size_t)(b * HW + pix) * 256 + head * 32 + lane] = acc;
}

// ---------------- launcher ----------------------------------------------------------
extern "C" void kernel_launch(void* const* d_in, const int* in_sizes, int n_in,
                              void* d_out, int out_size)
{
    const float* query   = (const float*)d_in[0];   // (4,3,256,64,64) == (4,768,64,64)
    const float* refp    = (const float*)d_in[1];   // (4,4096,3,2)
    const float* flat    = (const float*)d_in[2];   // (4,3,256,64,64) == (12,256,64,64)
    // d_in[3] spatial shapes, d_in[4] level start, d_in[5] padding mask (all-false): constants
    const float* w_value = (const float*)d_in[6];
    const float* b_value = (const float*)d_in[7];
    const float* w_off   = (const float*)d_in[8];
    const float* b_off   = (const float*)d_in[9];
    const float* w_attn  = (const float*)d_in[10];
    const float* b_attn  = (const float*)d_in[11];
    const float* w_out   = (const float*)d_in[12];
    const float* b_out   = (const float*)d_in[13];

    float *p_value_t, *p_off, *p_attn, *p_samp_t, *p_samp;
    cudaGetSymbolAddress((void**)&p_value_t, g_value_t);
    cudaGetSymbolAddress((void**)&p_off,     g_off);
    cudaGetSymbolAddress((void**)&p_attn,    g_attn);
    cudaGetSymbolAddress((void**)&p_samp_t,  g_samp_t);
    cudaGetSymbolAddress((void**)&p_samp,    g_samp);

    dim3 thr(16, 16);

    // 1) value conv: 12 images, 256 -> 256, token-major output (transpose fused)
    conv3x3_kernel<256, 16, true><<<dim3(2, 2, 12 * 16), thr>>>(flat, w_value, b_value, p_value_t, 256);
    // 2) offset conv: 4 images, 768 -> 192
    conv3x3_kernel<768, 16, false><<<dim3(2, 2, 4 * 12), thr>>>(query, w_off, b_off, p_off, 192);
    // 3) attn conv: 4 images, 768 -> 96
    conv3x3_kernel<768, 8, false><<<dim3(2, 2, 4 * 12), thr>>>(query, w_attn, b_attn, p_attn, 96);
    // 4) deformable attention sampling (+softmax), token-major out
    msda_kernel<<<(4 * 4096 * 8) / 8, 256>>>(p_value_t, p_off, p_attn, refp, p_samp_t);
    // 5) token-major -> NCHW
    transpose_kernel<<<dim3(256 / 32, 4096 / 32, 4), dim3(32, 8)>>>(p_samp_t, p_samp, 4096, 256);
    // 6) output conv: 4 images, 256 -> 256, write final result
    conv3x3_kernel<256, 16, false><<<dim3(2, 2, 4 * 16), thr>>>(p_samp, w_out, b_out, (float*)d_out, 256);
}

// round 4
// speedup vs baseline: 2.8774x; 2.8774x over previous
#include <cuda_runtime.h>
#include <cuda_bf16.h>
#include <cstdint>
#include <math.h>

#define HW 4096
#define CPA 36   // A smem channel pad (72B row stride -> conflict-free)
#define CPB 40   // B smem k pad (80B row stride, 16B aligned for cp.async)

// ---------------- device scratch (no allocation allowed) ----------------
__device__ __nv_bfloat16 g_q_hi   [4u * 4096u * 768u];
__device__ __nv_bfloat16 g_q_lo   [4u * 4096u * 768u];
__device__ __nv_bfloat16 g_flat_hi[12u * 4096u * 256u];
__device__ __nv_bfloat16 g_flat_lo[12u * 4096u * 256u];
__device__ __nv_bfloat16 g_samp_hi[4u * 4096u * 256u];
__device__ __nv_bfloat16 g_samp_lo[4u * 4096u * 256u];
__device__ float g_value_t[12u * 4096u * 256u];   // token-major value
__device__ float g_off_t  [4u * 4096u * 192u];    // token-major offsets
__device__ float g_attn_t [4u * 4096u * 96u];     // token-major attn logits
__device__ float g_samp_t [4u * 4096u * 256u];    // msda out token-major
__device__ __nv_bfloat16 g_wv_hi[9u * 256u * 256u], g_wv_lo[9u * 256u * 256u];
__device__ __nv_bfloat16 g_wo_hi[9u * 192u * 768u], g_wo_lo[9u * 192u * 768u];
__device__ __nv_bfloat16 g_wa_hi[9u * 96u  * 768u], g_wa_lo[9u * 96u  * 768u];
__device__ __nv_bfloat16 g_wu_hi[9u * 256u * 256u], g_wu_lo[9u * 256u * 256u];

// ---------------- small helpers ----------------
__device__ __forceinline__ unsigned ldsu(const __nv_bfloat16* p)
{
    return *reinterpret_cast<const unsigned*>(p);
}

__device__ __forceinline__ void mma16816(float* c, const unsigned* a, unsigned b0, unsigned b1)
{
    asm volatile("mma.sync.aligned.m16n8k16.row.col.f32.bf16.bf16.f32 "
        "{%0,%1,%2,%3}, {%4,%5,%6,%7}, {%8,%9}, {%0,%1,%2,%3};"
        : "+f"(c[0]), "+f"(c[1]), "+f"(c[2]), "+f"(c[3])
        : "r"(a[0]), "r"(a[1]), "r"(a[2]), "r"(a[3]), "r"(b0), "r"(b1));
}

__device__ __forceinline__ void cp16(unsigned daddr, const void* src, int srcsz)
{
    asm volatile("cp.async.cg.shared.global [%0], [%1], 16, %2;\n"
                 :: "r"(daddr), "l"(src), "r"(srcsz));
}

// ---------------- conversion kernels ----------------
// NCHW fp32 -> channel-last bf16 hi/lo (per image transpose)
__global__ void chlast_split(const float* __restrict__ in, __nv_bfloat16* __restrict__ hi,
                             __nv_bfloat16* __restrict__ lo, int C)
{
    __shared__ float t[32][33];
    int img = blockIdx.z;
    int p0 = blockIdx.x * 32, c0 = blockIdx.y * 32;
    int tx = threadIdx.x;
    for (int j = threadIdx.y; j < 32; j += 8)
        t[j][tx] = in[((size_t)img * C + c0 + j) * HW + p0 + tx];
    __syncthreads();
    for (int j = threadIdx.y; j < 32; j += 8) {
        float v = t[tx][j];
        __nv_bfloat16 h = __float2bfloat16(v);
        size_t o = ((size_t)img * HW + p0 + j) * C + c0 + tx;
        hi[o] = h;
        lo[o] = __float2bfloat16(v - __bfloat162float(h));
    }
}

// elementwise fp32 -> bf16 hi/lo (already channel-last)
__global__ void split_kernel(const float* __restrict__ in, __nv_bfloat16* __restrict__ hi,
                             __nv_bfloat16* __restrict__ lo, int n)
{
    int i = blockIdx.x * 256 + threadIdx.x;
    if (i < n) {
        float v = in[i];
        __nv_bfloat16 h = __float2bfloat16(v);
        hi[i] = h;
        lo[i] = __float2bfloat16(v - __bfloat162float(h));
    }
}

// w[co][ci][3][3] fp32 -> Bt[tap][co][ci] bf16 hi/lo
__global__ void wsplit_kernel(const float* __restrict__ w, __nv_bfloat16* __restrict__ hi,
                              __nv_bfloat16* __restrict__ lo, int cout, int cin)
{
    int i = blockIdx.x * 256 + threadIdx.x;
    int tot = 9 * cout * cin;
    if (i >= tot) return;
    int ci = i % cin; int r = i / cin; int co = r % cout; int tap = r / cout;
    float v = w[((size_t)co * cin + ci) * 9 + tap];
    __nv_bfloat16 h = __float2bfloat16(v);
    hi[i] = h;
    lo[i] = __float2bfloat16(v - __bfloat162float(h));
}

// ---------------- tensor-core implicit-GEMM 3x3 conv ----------------
// CTA: M=128 pixels (2 image rows) x N=128 couts.  K = CIN*9 via (cchunk of 32) x (9 taps).
// A halo tile staged once per cchunk; B slabs (32k x 128n) double-buffered via cp.async.
template<int CIN, bool TMAJOR>
__global__ void __launch_bounds__(256, 2)
conv_mma(const __nv_bfloat16* __restrict__ in_hi, const __nv_bfloat16* __restrict__ in_lo,
         const __nv_bfloat16* __restrict__ wt_hi, const __nv_bfloat16* __restrict__ wt_lo,
         const float* __restrict__ bias, float* __restrict__ out, int cout_total)
{
    extern __shared__ __nv_bfloat16 smem[];
    __nv_bfloat16* sAh = smem;                       // [4*66][CPA]
    __nv_bfloat16* sAl = sAh + 4 * 66 * CPA;
    __nv_bfloat16* sB  = sAl + 4 * 66 * CPA;         // [(buf*2+hl)*128 + n][CPB]
    const unsigned sB_u32 = (unsigned)__cvta_generic_to_shared(sB);

    const int tid = threadIdx.x;
    const int lane = tid & 31, warp = tid >> 5;
    const int gid = lane >> 2, tig = lane & 3;
    const int warpM = warp & 3, warpN = warp >> 2;

    const int Mbase = blockIdx.x * 128;
    const int Nbase = blockIdx.y * 128;
    const int img   = blockIdx.z;
    const int y0    = blockIdx.x * 2;

    float acc[2][8][4];
    #pragma unroll
    for (int ma = 0; ma < 2; ma++)
        #pragma unroll
        for (int na = 0; na < 8; na++)
            #pragma unroll
            for (int q = 0; q < 4; q++) acc[ma][na][q] = 0.f;

    #pragma unroll 1
    for (int cb = 0; cb < CIN; cb += 32) {
        __syncthreads();   // all warps done with A + both B buffers

        // ---- stage A halo: rows y0-1..y0+2, cols -1..64, 32 channels, hi+lo ----
        #pragma unroll 1
        for (int i = tid; i < 4 * 66 * 16; i += 256) {
            int rc = i >> 4, cp = i & 15;
            int r = rc / 66, col = rc % 66;
            int gy = y0 - 1 + r, gx = col - 1;
            unsigned vh = 0, vl = 0;
            if ((unsigned)gy < 64u && (unsigned)gx < 64u) {
                size_t g = ((size_t)(img * HW + gy * 64 + gx)) * CIN + cb + cp * 2;
                vh = ldsu(in_hi + g);
                vl = ldsu(in_lo + g);
            }
            *reinterpret_cast<unsigned*>(sAh + rc * CPA + cp * 2) = vh;
            *reinterpret_cast<unsigned*>(sAl + rc * CPA + cp * 2) = vl;
        }

        // ---- stage B for tap 0 into buf 0 ----
        #pragma unroll
        for (int j = 0; j < 2; j++) {
            int q = tid * 2 + j;
            int n = q >> 2, seg = q & 3;
            int co = Nbase + n;
            int cc = co < cout_total ? co : cout_total - 1;
            int sz = co < cout_total ? 16 : 0;
            size_t gsrc = ((size_t)cc) * CIN + cb + seg * 8;   // tap 0
            cp16(sB_u32 + (unsigned)(((0 * 128 + n) * CPB + seg * 8) * 2), wt_hi + gsrc, sz);
            cp16(sB_u32 + (unsigned)(((1 * 128 + n) * CPB + seg * 8) * 2), wt_lo + gsrc, sz);
        }
        asm volatile("cp.async.commit_group;\n" ::);

        #pragma unroll 1
        for (int tap = 0; tap < 9; tap++) {
            const int buf = tap & 1;
            __syncthreads();   // everyone done reading buf^1 (used at tap-1)
            if (tap + 1 < 9) {
                #pragma unroll
                for (int j = 0; j < 2; j++) {
                    int q = tid * 2 + j;
                    int n = q >> 2, seg = q & 3;
                    int co = Nbase + n;
                    int cc = co < cout_total ? co : cout_total - 1;
                    int sz = co < cout_total ? 16 : 0;
                    size_t gsrc = ((size_t)((tap + 1) * cout_total + cc)) * CIN + cb + seg * 8;
                    cp16(sB_u32 + (unsigned)(((((buf ^ 1) * 2 + 0) * 128 + n) * CPB + seg * 8) * 2), wt_hi + gsrc, sz);
                    cp16(sB_u32 + (unsigned)(((((buf ^ 1) * 2 + 1) * 128 + n) * CPB + seg * 8) * 2), wt_lo + gsrc, sz);
                }
                asm volatile("cp.async.commit_group;\n" ::);
                asm volatile("cp.async.wait_group 1;\n" ::);
            } else {
                asm volatile("cp.async.wait_group 0;\n" ::);
            }
            __syncthreads();   // buf contents visible to all

            const int dy = tap / 3, dx = tap % 3;
            #pragma unroll
            for (int ks = 0; ks < 2; ks++) {
                const int kb = ks * 16;
                unsigned ra_h[2][4];
                unsigned ra_l[2][4];
                #pragma unroll
                for (int ma = 0; ma < 2; ma++) {
                    int pixbase = warpM * 32 + ma * 16;
                    int yy = (pixbase >> 6) + dy;
                    int xx = (pixbase & 63) + gid + dx;
                    int ofs0 = (yy * 66 + xx) * CPA + kb + tig * 2;
                    int ofs8 = (yy * 66 + xx + 8) * CPA + kb + tig * 2;
                    ra_h[ma][0] = ldsu(sAh + ofs0);
                    ra_h[ma][1] = ldsu(sAh + ofs8);
                    ra_h[ma][2] = ldsu(sAh + ofs0 + 8);
                    ra_h[ma][3] = ldsu(sAh + ofs8 + 8);
                    ra_l[ma][0] = ldsu(sAl + ofs0);
                    ra_l[ma][1] = ldsu(sAl + ofs8);
                    ra_l[ma][2] = ldsu(sAl + ofs0 + 8);
                    ra_l[ma][3] = ldsu(sAl + ofs8 + 8);
                }
                #pragma unroll
                for (int na = 0; na < 8; na++) {
                    int n = warpN * 64 + na * 8 + gid;
                    int obh = ((buf * 2 + 0) * 128 + n) * CPB + kb + tig * 2;
                    int obl = ((buf * 2 + 1) * 128 + n) * CPB + kb + tig * 2;
                    unsigned rbh0 = ldsu(sB + obh);
                    unsigned rbh1 = ldsu(sB + obh + 8);
                    unsigned rbl0 = ldsu(sB + obl);
                    unsigned rbl1 = ldsu(sB + obl + 8);
                    #pragma unroll
                    for (int ma = 0; ma < 2; ma++) {
                        mma16816(acc[ma][na], ra_h[ma], rbh0, rbh1);
                        mma16816(acc[ma][na], ra_h[ma], rbl0, rbl1);
                        mma16816(acc[ma][na], ra_l[ma], rbh0, rbh1);
                    }
                }
            }
        }
    }

    // ---- epilogue ----
    #pragma unroll
    for (int ma = 0; ma < 2; ma++) {
        int pix = Mbase + warpM * 32 + ma * 16 + gid;
        #pragma unroll
        for (int na = 0; na < 8; na++) {
            int co = Nbase + warpN * 64 + na * 8 + tig * 2;
            if (co < cout_total) {
                float bv0 = bias[co], bv1 = bias[co + 1];
                if (TMAJOR) {
                    float2* p0 = reinterpret_cast<float2*>(out + ((size_t)img * HW + pix) * cout_total + co);
                    float2* p1 = reinterpret_cast<float2*>(out + ((size_t)img * HW + pix + 8) * cout_total + co);
                    *p0 = make_float2(acc[ma][na][0] + bv0, acc[ma][na][1] + bv1);
                    *p1 = make_float2(acc[ma][na][2] + bv0, acc[ma][na][3] + bv1);
                } else {
                    out[((size_t)img * cout_total + co)     * HW + pix]     = acc[ma][na][0] + bv0;
                    out[((size_t)img * cout_total + co + 1) * HW + pix]     = acc[ma][na][1] + bv1;
                    out[((size_t)img * cout_total + co)     * HW + pix + 8] = acc[ma][na][2] + bv0;
                    out[((size_t)img * cout_total + co + 1) * HW + pix + 8] = acc[ma][na][3] + bv1;
                }
            }
        }
    }
}

// ---------------- MSDA sampling + fused softmax (token-major I/O) -------------------
__global__ __launch_bounds__(256)
void msda_kernel(const float* __restrict__ value_t, const float* __restrict__ off_t,
                 const float* __restrict__ attn_t, const float* __restrict__ refp,
                 float* __restrict__ out_t)
{
    int gw = blockIdx.x * 8 + (threadIdx.x >> 5);   // (b*4096 + pix)*8 + head
    int lane = threadIdx.x & 31;
    int head = gw & 7;
    int pix  = (gw >> 3) & 4095;
    int b    = gw >> 15;

    size_t tok = (size_t)b * HW + pix;
    const float* ap = attn_t + tok * 96 + head * 12;
    const float* op = off_t + tok * 192;

    float lg[12]; float mx = -1e30f;
    #pragma unroll
    for (int j = 0; j < 12; j++) { lg[j] = ap[j]; mx = fmaxf(mx, lg[j]); }
    float den = 0.f;
    #pragma unroll
    for (int j = 0; j < 12; j++) { lg[j] = expf(lg[j] - mx); den += lg[j]; }
    float rden = 1.f / den;

    float acc = 0.f;
    #pragma unroll
    for (int l = 0; l < 3; l++) {
        float rx = refp[(tok * 3 + l) * 2 + 0];
        float ry = refp[(tok * 3 + l) * 2 + 1];
        const float* vb = value_t + ((size_t)(b * 3 + l) * HW) * 256 + head * 32 + lane;
        #pragma unroll
        for (int p = 0; p < 4; p++) {
            int ch = ((head * 3 + l) * 4 + p) * 2;
            float ox = op[ch], oy = op[ch + 1];
            float a = lg[l * 4 + p] * rden;
            float xf = rx * 64.f + ox - 0.5f;
            float yf = ry * 64.f + oy - 0.5f;
            float x0f = floorf(xf), y0f = floorf(yf);
            int x0 = (int)x0f, y0 = (int)y0f;
            float lx = xf - x0f, ly = yf - y0f;
            float w00 = (1.f - lx) * (1.f - ly) * a;
            float w10 = lx * (1.f - ly) * a;
            float w01 = (1.f - lx) * ly * a;
            float w11 = lx * ly * a;
            if ((unsigned)x0       < 64u && (unsigned)y0       < 64u) acc += w00 * vb[(size_t)(y0 * 64 + x0) * 256];
            if ((unsigned)(x0 + 1) < 64u && (unsigned)y0       < 64u) acc += w10 * vb[(size_t)(y0 * 64 + x0 + 1) * 256];
            if ((unsigned)x0       < 64u && (unsigned)(y0 + 1) < 64u) acc += w01 * vb[(size_t)((y0 + 1) * 64 + x0) * 256];
            if ((unsigned)(x0 + 1) < 64u && (unsigned)(y0 + 1) < 64u) acc += w11 * vb[(size_t)((y0 + 1) * 64 + x0 + 1) * 256];
        }
    }
    out_t[tok * 256 + head * 32 + lane] = acc;
}

// ---------------- launcher ----------------------------------------------------------
extern "C" void kernel_launch(void* const* d_in, const int* in_sizes, int n_in,
                              void* d_out, int out_size)
{
    const float* query   = (const float*)d_in[0];
    const float* refp    = (const float*)d_in[1];
    const float* flat    = (const float*)d_in[2];
    const float* w_value = (const float*)d_in[6];
    const float* b_value = (const float*)d_in[7];
    const float* w_off   = (const float*)d_in[8];
    const float* b_off   = (const float*)d_in[9];
    const float* w_attn  = (const float*)d_in[10];
    const float* b_attn  = (const float*)d_in[11];
    const float* w_out   = (const float*)d_in[12];
    const float* b_out   = (const float*)d_in[13];

    __nv_bfloat16 *q_hi, *q_lo, *f_hi, *f_lo, *s_hi, *s_lo;
    __nv_bfloat16 *wv_hi, *wv_lo, *wo_hi, *wo_lo, *wa_hi, *wa_lo, *wu_hi, *wu_lo;
    float *value_t, *off_t, *attn_t, *samp_t;
    cudaGetSymbolAddress((void**)&q_hi, g_q_hi);   cudaGetSymbolAddress((void**)&q_lo, g_q_lo);
    cudaGetSymbolAddress((void**)&f_hi, g_flat_hi);cudaGetSymbolAddress((void**)&f_lo, g_flat_lo);
    cudaGetSymbolAddress((void**)&s_hi, g_samp_hi);cudaGetSymbolAddress((void**)&s_lo, g_samp_lo);
    cudaGetSymbolAddress((void**)&wv_hi, g_wv_hi); cudaGetSymbolAddress((void**)&wv_lo, g_wv_lo);
    cudaGetSymbolAddress((void**)&wo_hi, g_wo_hi); cudaGetSymbolAddress((void**)&wo_lo, g_wo_lo);
    cudaGetSymbolAddress((void**)&wa_hi, g_wa_hi); cudaGetSymbolAddress((void**)&wa_lo, g_wa_lo);
    cudaGetSymbolAddress((void**)&wu_hi, g_wu_hi); cudaGetSymbolAddress((void**)&wu_lo, g_wu_lo);
    cudaGetSymbolAddress((void**)&value_t, g_value_t);
    cudaGetSymbolAddress((void**)&off_t,   g_off_t);
    cudaGetSymbolAddress((void**)&attn_t,  g_attn_t);
    cudaGetSymbolAddress((void**)&samp_t,  g_samp_t);

    const int SMEM = (2 * 4 * 66 * CPA + 2 * 2 * 128 * CPB) * 2;   // bytes
    cudaFuncSetAttribute(conv_mma<256, true>,  cudaFuncAttributeMaxDynamicSharedMemorySize, SMEM);
    cudaFuncSetAttribute(conv_mma<768, true>,  cudaFuncAttributeMaxDynamicSharedMemorySize, SMEM);
    cudaFuncSetAttribute(conv_mma<256, false>, cudaFuncAttributeMaxDynamicSharedMemorySize, SMEM);

    // conversions
    chlast_split<<<dim3(128, 8, 12), dim3(32, 8)>>>(flat, f_hi, f_lo, 256);
    chlast_split<<<dim3(128, 24, 4), dim3(32, 8)>>>(query, q_hi, q_lo, 768);
    wsplit_kernel<<<(9 * 256 * 256 + 255) / 256, 256>>>(w_value, wv_hi, wv_lo, 256, 256);
    wsplit_kernel<<<(9 * 192 * 768 + 255) / 256, 256>>>(w_off,   wo_hi, wo_lo, 192, 768);
    wsplit_kernel<<<(9 * 96  * 768 + 255) / 256, 256>>>(w_attn,  wa_hi, wa_lo, 96,  768);
    wsplit_kernel<<<(9 * 256 * 256 + 255) / 256, 256>>>(w_out,   wu_hi, wu_lo, 256, 256);

    // convs (tensor core)
    conv_mma<256, true><<<dim3(32, 2, 12), 256, SMEM>>>(f_hi, f_lo, wv_hi, wv_lo, b_value, value_t, 256);
    conv_mma<768, true><<<dim3(32, 2, 4),  256, SMEM>>>(q_hi, q_lo, wo_hi, wo_lo, b_off,   off_t,   192);
    conv_mma<768, true><<<dim3(32, 1, 4),  256, SMEM>>>(q_hi, q_lo, wa_hi, wa_lo, b_attn,  attn_t,  96);

    // msda sampling
    msda_kernel<<<(4 * HW * 8) / 8, 256>>>(value_t, off_t, attn_t, refp, samp_t);

    // split msda output (already token-major/channel-last)
    split_kernel<<<(4 * HW * 256 + 255) / 256, 256>>>(samp_t, s_hi, s_lo, 4 * HW * 256);

    // output conv -> NCHW d_out
    conv_mma<256, false><<<dim3(32, 2, 4), 256, SMEM>>>(s_hi, s_lo, wu_hi, wu_lo, b_out, (float*)d_out, 256);
}

// round 5
// speedup vs baseline: 3.9163x; 1.3611x over previous
#include <cuda_runtime.h>
#include <cuda_bf16.h>
#include <cstdint>
#include <math.h>

#define HW 4096
#define CPA_B 80                    // A smem row stride (bytes), 16B-aligned for ldmatrix
#define CPB_B 80                    // B smem row stride (bytes)
#define A_POS (4 * 66)              // halo positions per chunk tile
#define A_HALF_B (A_POS * CPA_B)    // 21120 bytes per hi/lo half
#define B_SLOT_B (2 * 128 * CPB_B)  // 20480 bytes per slot (hi+lo)
#define SMEM_BYTES (2 * A_HALF_B + 3 * B_SLOT_B)   // 103680

// ---------------- device scratch ----------------
__device__ __nv_bfloat16 g_q_hi   [4u * 4096u * 768u];
__device__ __nv_bfloat16 g_q_lo   [4u * 4096u * 768u];
__device__ __nv_bfloat16 g_flat_hi[12u * 4096u * 256u];
__device__ __nv_bfloat16 g_flat_lo[12u * 4096u * 256u];
__device__ __nv_bfloat16 g_samp_hi[4u * 4096u * 256u];
__device__ __nv_bfloat16 g_samp_lo[4u * 4096u * 256u];
__device__ float g_value_t[12u * 4096u * 256u];
__device__ float g_off_t  [4u * 4096u * 192u];
__device__ float g_attn_t [4u * 4096u * 96u];
__device__ __nv_bfloat16 g_wv_hi[9u * 256u * 256u], g_wv_lo[9u * 256u * 256u];
__device__ __nv_bfloat16 g_wo_hi[9u * 192u * 768u], g_wo_lo[9u * 192u * 768u];
__device__ __nv_bfloat16 g_wa_hi[9u * 96u  * 768u], g_wa_lo[9u * 96u  * 768u];
__device__ __nv_bfloat16 g_wu_hi[9u * 256u * 256u], g_wu_lo[9u * 256u * 256u];

// ---------------- helpers ----------------
__device__ __forceinline__ void mma16816(float* c, const unsigned* a, unsigned b0, unsigned b1)
{
    asm volatile("mma.sync.aligned.m16n8k16.row.col.f32.bf16.bf16.f32 "
        "{%0,%1,%2,%3}, {%4,%5,%6,%7}, {%8,%9}, {%0,%1,%2,%3};"
        : "+f"(c[0]), "+f"(c[1]), "+f"(c[2]), "+f"(c[3])
        : "r"(a[0]), "r"(a[1]), "r"(a[2]), "r"(a[3]), "r"(b0), "r"(b1));
}

__device__ __forceinline__ void cp16(unsigned daddr, const void* src, int srcsz)
{
    asm volatile("cp.async.cg.shared.global [%0], [%1], 16, %2;\n"
                 :: "r"(daddr), "l"(src), "r"(srcsz));
}

__device__ __forceinline__ void ldsm4(unsigned* d, unsigned saddr)
{
    asm volatile("ldmatrix.sync.aligned.m8n8.x4.shared.b16 {%0,%1,%2,%3}, [%4];"
        : "=r"(d[0]), "=r"(d[1]), "=r"(d[2]), "=r"(d[3]) : "r"(saddr));
}

// ---------------- conversion kernels ----------------
__global__ void chlast_split(const float* __restrict__ in, __nv_bfloat16* __restrict__ hi,
                             __nv_bfloat16* __restrict__ lo, int C)
{
    __shared__ float t[32][33];
    int img = blockIdx.z;
    int p0 = blockIdx.x * 32, c0 = blockIdx.y * 32;
    int tx = threadIdx.x;
    for (int j = threadIdx.y; j < 32; j += 8)
        t[j][tx] = in[((size_t)img * C + c0 + j) * HW + p0 + tx];
    __syncthreads();
    for (int j = threadIdx.y; j < 32; j += 8) {
        float v = t[tx][j];
        __nv_bfloat16 h = __float2bfloat16(v);
        size_t o = ((size_t)img * HW + p0 + j) * C + c0 + tx;
        hi[o] = h;
        lo[o] = __float2bfloat16(v - __bfloat162float(h));
    }
}

__global__ void wsplit_kernel(const float* __restrict__ w, __nv_bfloat16* __restrict__ hi,
                              __nv_bfloat16* __restrict__ lo, int cout, int cin)
{
    int i = blockIdx.x * 256 + threadIdx.x;
    int tot = 9 * cout * cin;
    if (i >= tot) return;
    int ci = i % cin; int r = i / cin; int co = r % cout; int tap = r / cout;
    float v = w[((size_t)co * cin + ci) * 9 + tap];
    __nv_bfloat16 h = __float2bfloat16(v);
    hi[i] = h;
    lo[i] = __float2bfloat16(v - __bfloat162float(h));
}

// ---------------- tensor-core implicit-GEMM 3x3 conv ----------------
// CTA: M=128 pixels (2 rows) x N=128 couts. Per 32-ch chunk: halo tile staged once
// (cp.async, zero-fill pad), 9 taps with 3-slot double... triple-buffered B slabs,
// one __syncthreads per tap. Fragments loaded via ldmatrix.x4.
template<int CIN, bool TMAJOR>
__global__ void __launch_bounds__(256, 2)
conv_mma(const __nv_bfloat16* __restrict__ in_hi, const __nv_bfloat16* __restrict__ in_lo,
         const __nv_bfloat16* __restrict__ wt_hi, const __nv_bfloat16* __restrict__ wt_lo,
         const float* __restrict__ bias, float* __restrict__ out, int cout_total)
{
    extern __shared__ unsigned char smem_raw[];
    const unsigned sm_base = (unsigned)__cvta_generic_to_shared(smem_raw);
    const unsigned sA  = sm_base;                     // A hi then lo
    const unsigned sBb = sm_base + 2 * A_HALF_B;      // 3 slots x (hi,lo)

    const int tid = threadIdx.x;
    const int lane = tid & 31, warp = tid >> 5;
    const int gid = lane >> 2, tig = lane & 3;        // epilogue fragment coords
    const int jj = lane >> 3, rr = lane & 7;          // ldmatrix lane coords
    const int warpM = warp & 3, warpN = warp >> 2;

    const int Mbase = blockIdx.x * 128;
    const int Nbase = blockIdx.y * 128;
    const int img   = blockIdx.z;
    const int y0    = blockIdx.x * 2;

    const int NTAP_TOT = (CIN / 32) * 9;

    float acc[2][8][4];
    #pragma unroll
    for (int ma = 0; ma < 2; ma++)
        #pragma unroll
        for (int na = 0; na < 8; na++)
            #pragma unroll
            for (int q = 0; q < 4; q++) acc[ma][na][q] = 0.f;

    // issue B slab for global tap g into slot g%3, always commit (group counting)
    auto issue_b = [&](int g) {
        if (g < NTAP_TOT) {
            int cbb = (g / 9) * 32;
            int tp  = g % 9;
            int slot = g % 3;
            #pragma unroll
            for (int j2 = 0; j2 < 2; j2++) {
                int q = tid * 2 + j2;
                int n = q >> 2, seg = q & 3;
                int co = Nbase + n;
                int cc = co < cout_total ? co : 0;
                int sz = co < cout_total ? 16 : 0;
                size_t gsrc = ((size_t)(tp * cout_total + cc)) * CIN + cbb + seg * 8;
                cp16(sBb + (unsigned)(((slot * 2 + 0) * 128 + n) * CPB_B + seg * 16), wt_hi + gsrc, sz);
                cp16(sBb + (unsigned)(((slot * 2 + 1) * 128 + n) * CPB_B + seg * 16), wt_lo + gsrc, sz);
            }
        }
        asm volatile("cp.async.commit_group;\n" ::);
    };

    issue_b(0);
    issue_b(1);

    int g = 0;
    #pragma unroll 1
    for (int cb = 0; cb < CIN; cb += 32) {
        __syncthreads();   // all reads of A (previous chunk) complete

        // ---- stage A halo via cp.async (zero-fill OOB) ----
        #pragma unroll 1
        for (int i = tid; i < A_POS * 8; i += 256) {
            int pos = i >> 3, sub = i & 7;
            int hf = sub >> 2, seg = sub & 3;
            int ry = pos / 66, col = pos % 66;
            int gy = y0 - 1 + ry, gx = col - 1;
            int ok = ((unsigned)gy < 64u && (unsigned)gx < 64u) ? 16 : 0;
            int gyc = gy < 0 ? 0 : (gy > 63 ? 63 : gy);
            int gxc = gx < 0 ? 0 : (gx > 63 ? 63 : gx);
            const __nv_bfloat16* src = (hf ? in_lo : in_hi)
                + ((size_t)(img * HW + gyc * 64 + gxc)) * CIN + cb + seg * 8;
            cp16(sA + (unsigned)(hf * A_HALF_B + pos * CPA_B + seg * 16), src, ok);
        }
        asm volatile("cp.async.commit_group;\n" ::);

        #pragma unroll 1
        for (int tap = 0; tap < 9; tap++, g++) {
            if (tap == 0) asm volatile("cp.async.wait_group 0;\n" ::);  // drain incl. A group
            else          asm volatile("cp.async.wait_group 1;\n" ::);  // B(g) ready
            __syncthreads();   // cross-thread visibility

            const int dy = tap / 3, dx = tap - dy * 3;
            const int slot = g % 3;
            const unsigned sBh = sBb + (unsigned)((slot * 2 + 0) * 128 * CPB_B);
            const unsigned sBl = sBb + (unsigned)((slot * 2 + 1) * 128 * CPB_B);

            #pragma unroll
            for (int ks = 0; ks < 2; ks++) {
                const int kb2 = ks * 32;   // k byte offset within 64B row
                unsigned ra_h[2][4], ra_l[2][4];
                #pragma unroll
                for (int ma = 0; ma < 2; ma++) {
                    int pixel = warpM * 32 + ma * 16 + ((jj & 1) << 3) + rr;
                    int yy = (pixel >> 6) + dy;
                    int xx = (pixel & 63) + dx;
                    unsigned aofs = (unsigned)((yy * 66 + xx) * CPA_B + kb2 + ((jj >> 1) << 4));
                    ldsm4(ra_h[ma], sA + aofs);
                    ldsm4(ra_l[ma], sA + A_HALF_B + aofs);
                }
                #pragma unroll
                for (int np = 0; np < 4; np++) {
                    int n = warpN * 64 + (np * 2 + (jj >> 1)) * 8 + rr;
                    unsigned bofs = (unsigned)(n * CPB_B + kb2 + ((jj & 1) << 4));
                    unsigned rbh[4], rbl[4];
                    ldsm4(rbh, sBh + bofs);
                    ldsm4(rbl, sBl + bofs);
                    #pragma unroll
                    for (int ma = 0; ma < 2; ma++) {
                        mma16816(acc[ma][np * 2],     ra_h[ma], rbh[0], rbh[1]);
                        mma16816(acc[ma][np * 2],     ra_h[ma], rbl[0], rbl[1]);
                        mma16816(acc[ma][np * 2],     ra_l[ma], rbh[0], rbh[1]);
                        mma16816(acc[ma][np * 2 + 1], ra_h[ma], rbh[2], rbh[3]);
                        mma16816(acc[ma][np * 2 + 1], ra_h[ma], rbl[2], rbl[3]);
                        mma16816(acc[ma][np * 2 + 1], ra_l[ma], rbh[2], rbh[3]);
                    }
                }
            }
            issue_b(g + 2);   // safe: slot (g+2)%3 last read at tap g-1, barrier passed
        }
    }

    // ---- epilogue ----
    #pragma unroll
    for (int ma = 0; ma < 2; ma++) {
        int pix = Mbase + warpM * 32 + ma * 16 + gid;
        #pragma unroll
        for (int na = 0; na < 8; na++) {
            int co = Nbase + warpN * 64 + na * 8 + tig * 2;
            if (co < cout_total) {
                float bv0 = bias[co], bv1 = bias[co + 1];
                if (TMAJOR) {
                    float2* p0 = reinterpret_cast<float2*>(out + ((size_t)img * HW + pix) * cout_total + co);
                    float2* p1 = reinterpret_cast<float2*>(out + ((size_t)img * HW + pix + 8) * cout_total + co);
                    *p0 = make_float2(acc[ma][na][0] + bv0, acc[ma][na][1] + bv1);
                    *p1 = make_float2(acc[ma][na][2] + bv0, acc[ma][na][3] + bv1);
                } else {
                    out[((size_t)img * cout_total + co)     * HW + pix]     = acc[ma][na][0] + bv0;
                    out[((size_t)img * cout_total + co + 1) * HW + pix]     = acc[ma][na][1] + bv1;
                    out[((size_t)img * cout_total + co)     * HW + pix + 8] = acc[ma][na][2] + bv0;
                    out[((size_t)img * cout_total + co + 1) * HW + pix + 8] = acc[ma][na][3] + bv1;
                }
            }
        }
    }
}

// ---------------- MSDA sampling + fused softmax; writes bf16 hi/lo -----------------
__global__ __launch_bounds__(256)
void msda_kernel(const float* __restrict__ value_t, const float* __restrict__ off_t,
                 const float* __restrict__ attn_t, const float* __restrict__ refp,
                 __nv_bfloat16* __restrict__ out_hi, __nv_bfloat16* __restrict__ out_lo)
{
    int gw = blockIdx.x * 8 + (threadIdx.x >> 5);
    int lane = threadIdx.x & 31;
    int head = gw & 7;
    int pix  = (gw >> 3) & 4095;
    int b    = gw >> 15;

    size_t tok = (size_t)b * HW + pix;
    const float* ap = attn_t + tok * 96 + head * 12;
    const float* op = off_t + tok * 192;

    float lg[12]; float mx = -1e30f;
    #pragma unroll
    for (int j = 0; j < 12; j++) { lg[j] = ap[j]; mx = fmaxf(mx, lg[j]); }
    float den = 0.f;
    #pragma unroll
    for (int j = 0; j < 12; j++) { lg[j] = expf(lg[j] - mx); den += lg[j]; }
    float rden = 1.f / den;

    float acc = 0.f;
    #pragma unroll
    for (int l = 0; l < 3; l++) {
        float rx = refp[(tok * 3 + l) * 2 + 0];
        float ry = refp[(tok * 3 + l) * 2 + 1];
        const float* vb = value_t + ((size_t)(b * 3 + l) * HW) * 256 + head * 32 + lane;
        #pragma unroll
        for (int p = 0; p < 4; p++) {
            int ch = ((head * 3 + l) * 4 + p) * 2;
            float ox = op[ch], oy = op[ch + 1];
            float a = lg[l * 4 + p] * rden;
            float xf = rx * 64.f + ox - 0.5f;
            float yf = ry * 64.f + oy - 0.5f;
            float x0f = floorf(xf), y0f = floorf(yf);
            int x0 = (int)x0f, y0 = (int)y0f;
            float lx = xf - x0f, ly = yf - y0f;
            float w00 = (1.f - lx) * (1.f - ly) * a;
            float w10 = lx * (1.f - ly) * a;
            float w01 = (1.f - lx) * ly * a;
            float w11 = lx * ly * a;
            if ((unsigned)x0       < 64u && (unsigned)y0       < 64u) acc += w00 * vb[(size_t)(y0 * 64 + x0) * 256];
            if ((unsigned)(x0 + 1) < 64u && (unsigned)y0       < 64u) acc += w10 * vb[(size_t)(y0 * 64 + x0 + 1) * 256];
            if ((unsigned)x0       < 64u && (unsigned)(y0 + 1) < 64u) acc += w01 * vb[(size_t)((y0 + 1) * 64 + x0) * 256];
            if ((unsigned)(x0 + 1) < 64u && (unsigned)(y0 + 1) < 64u) acc += w11 * vb[(size_t)((y0 + 1) * 64 + x0 + 1) * 256];
        }
    }
    __nv_bfloat16 h = __float2bfloat16(acc);
    size_t o = tok * 256 + head * 32 + lane;
    out_hi[o] = h;
    out_lo[o] = __float2bfloat16(acc - __bfloat162float(h));
}

// ---------------- launcher ----------------------------------------------------------
extern "C" void kernel_launch(void* const* d_in, const int* in_sizes, int n_in,
                              void* d_out, int out_size)
{
    const float* query   = (const float*)d_in[0];
    const float* refp    = (const float*)d_in[1];
    const float* flat    = (const float*)d_in[2];
    const float* w_value = (const float*)d_in[6];
    const float* b_value = (const float*)d_in[7];
    const float* w_off   = (const float*)d_in[8];
    const float* b_off   = (const float*)d_in[9];
    const float* w_attn  = (const float*)d_in[10];
    const float* b_attn  = (const float*)d_in[11];
    const float* w_out   = (const float*)d_in[12];
    const float* b_out   = (const float*)d_in[13];

    __nv_bfloat16 *q_hi, *q_lo, *f_hi, *f_lo, *s_hi, *s_lo;
    __nv_bfloat16 *wv_hi, *wv_lo, *wo_hi, *wo_lo, *wa_hi, *wa_lo, *wu_hi, *wu_lo;
    float *value_t, *off_t, *attn_t;
    cudaGetSymbolAddress((void**)&q_hi, g_q_hi);   cudaGetSymbolAddress((void**)&q_lo, g_q_lo);
    cudaGetSymbolAddress((void**)&f_hi, g_flat_hi);cudaGetSymbolAddress((void**)&f_lo, g_flat_lo);
    cudaGetSymbolAddress((void**)&s_hi, g_samp_hi);cudaGetSymbolAddress((void**)&s_lo, g_samp_lo);
    cudaGetSymbolAddress((void**)&wv_hi, g_wv_hi); cudaGetSymbolAddress((void**)&wv_lo, g_wv_lo);
    cudaGetSymbolAddress((void**)&wo_hi, g_wo_hi); cudaGetSymbolAddress((void**)&wo_lo, g_wo_lo);
    cudaGetSymbolAddress((void**)&wa_hi, g_wa_hi); cudaGetSymbolAddress((void**)&wa_lo, g_wa_lo);
    cudaGetSymbolAddress((void**)&wu_hi, g_wu_hi); cudaGetSymbolAddress((void**)&wu_lo, g_wu_lo);
    cudaGetSymbolAddress((void**)&value_t, g_value_t);
    cudaGetSymbolAddress((void**)&off_t,   g_off_t);
    cudaGetSymbolAddress((void**)&attn_t,  g_attn_t);

    cudaFuncSetAttribute(conv_mma<256, true>,  cudaFuncAttributeMaxDynamicSharedMemorySize, SMEM_BYTES);
    cudaFuncSetAttribute(conv_mma<768, true>,  cudaFuncAttributeMaxDynamicSharedMemorySize, SMEM_BYTES);
    cudaFuncSetAttribute(conv_mma<256, false>, cudaFuncAttributeMaxDynamicSharedMemorySize, SMEM_BYTES);

    // launches 0..4 (ncu -s 5 profiles launch index 5 = value conv)
    chlast_split<<<dim3(128, 8, 12), dim3(32, 8)>>>(flat, f_hi, f_lo, 256);
    chlast_split<<<dim3(128, 24, 4), dim3(32, 8)>>>(query, q_hi, q_lo, 768);
    wsplit_kernel<<<(9 * 256 * 256 + 255) / 256, 256>>>(w_value, wv_hi, wv_lo, 256, 256);
    wsplit_kernel<<<(9 * 192 * 768 + 255) / 256, 256>>>(w_off,   wo_hi, wo_lo, 192, 768);
    wsplit_kernel<<<(9 * 96  * 768 + 255) / 256, 256>>>(w_attn,  wa_hi, wa_lo, 96,  768);

    // launch 5: value conv (profiled)
    conv_mma<256, true><<<dim3(32, 2, 12), 256, SMEM_BYTES>>>(f_hi, f_lo, wv_hi, wv_lo, b_value, value_t, 256);

    wsplit_kernel<<<(9 * 256 * 256 + 255) / 256, 256>>>(w_out, wu_hi, wu_lo, 256, 256);

    conv_mma<768, true><<<dim3(32, 2, 4), 256, SMEM_BYTES>>>(q_hi, q_lo, wo_hi, wo_lo, b_off,  off_t,  192);
    conv_mma<768, true><<<dim3(32, 1, 4), 256, SMEM_BYTES>>>(q_hi, q_lo, wa_hi, wa_lo, b_attn, attn_t, 96);

    msda_kernel<<<(4 * HW * 8) / 8, 256>>>(value_t, off_t, attn_t, refp, s_hi, s_lo);

    conv_mma<256, false><<<dim3(32, 2, 4), 256, SMEM_BYTES>>>(s_hi, s_lo, wu_hi, wu_lo, b_out, (float*)d_out, 256);
}

// round 6
// speedup vs baseline: 4.3105x; 1.1007x over previous
#include <cuda_runtime.h>
#include <cuda_bf16.h>
#include <cstdint>
#include <math.h>

#define HW 4096
#define CPA_B 80                    // A smem row stride (bytes), 16B-aligned for ldmatrix
#define CPB_B 80                    // B smem row stride (bytes)
#define A_POS (4 * 66)              // halo positions per chunk tile
#define A_HALF_B (A_POS * CPA_B)    // bytes per hi/lo half
#define B_SLOT_B (2 * 128 * CPB_B)  // slot sized for 128 rows (96 uses a subset)
#define SMEM_BYTES (2 * A_HALF_B + 3 * B_SLOT_B)   // 103680

// ---------------- device scratch ----------------
__device__ __nv_bfloat16 g_q_hi   [4u * 4096u * 768u];
__device__ __nv_bfloat16 g_q_lo   [4u * 4096u * 768u];
__device__ __nv_bfloat16 g_flat_hi[12u * 4096u * 256u];
__device__ __nv_bfloat16 g_flat_lo[12u * 4096u * 256u];
__device__ __nv_bfloat16 g_samp_hi[4u * 4096u * 256u];
__device__ __nv_bfloat16 g_samp_lo[4u * 4096u * 256u];
__device__ float g_value_t[12u * 4096u * 256u];
__device__ float g_oa_t   [4u * 4096u * 288u];        // merged off(0:192)+attn(192:288), token-major
__device__ float g_boa    [288];
__device__ __nv_bfloat16 g_wv_hi [9u * 256u * 256u], g_wv_lo [9u * 256u * 256u];
__device__ __nv_bfloat16 g_woa_hi[9u * 288u * 768u], g_woa_lo[9u * 288u * 768u];
__device__ __nv_bfloat16 g_wu_hi [9u * 256u * 256u], g_wu_lo [9u * 256u * 256u];

// ---------------- helpers ----------------
__device__ __forceinline__ void mma16816(float* c, const unsigned* a, unsigned b0, unsigned b1)
{
    asm volatile("mma.sync.aligned.m16n8k16.row.col.f32.bf16.bf16.f32 "
        "{%0,%1,%2,%3}, {%4,%5,%6,%7}, {%8,%9}, {%0,%1,%2,%3};"
        : "+f"(c[0]), "+f"(c[1]), "+f"(c[2]), "+f"(c[3])
        : "r"(a[0]), "r"(a[1]), "r"(a[2]), "r"(a[3]), "r"(b0), "r"(b1));
}

__device__ __forceinline__ void cp16(unsigned daddr, const void* src, int srcsz)
{
    asm volatile("cp.async.cg.shared.global [%0], [%1], 16, %2;\n"
                 :: "r"(daddr), "l"(src), "r"(srcsz));
}

__device__ __forceinline__ void ldsm4(unsigned* d, unsigned saddr)
{
    asm volatile("ldmatrix.sync.aligned.m8n8.x4.shared.b16 {%0,%1,%2,%3}, [%4];"
        : "=r"(d[0]), "=r"(d[1]), "=r"(d[2]), "=r"(d[3]) : "r"(saddr));
}

// ---------------- conversion kernels ----------------
__global__ void chlast_split(const float* __restrict__ in, __nv_bfloat16* __restrict__ hi,
                             __nv_bfloat16* __restrict__ lo, int C)
{
    __shared__ float t[32][33];
    int img = blockIdx.z;
    int p0 = blockIdx.x * 32, c0 = blockIdx.y * 32;
    int tx = threadIdx.x;
    for (int j = threadIdx.y; j < 32; j += 8)
        t[j][tx] = in[((size_t)img * C + c0 + j) * HW + p0 + tx];
    __syncthreads();
    for (int j = threadIdx.y; j < 32; j += 8) {
        float v = t[tx][j];
        __nv_bfloat16 h = __float2bfloat16(v);
        size_t o = ((size_t)img * HW + p0 + j) * C + c0 + tx;
        hi[o] = h;
        lo[o] = __float2bfloat16(v - __bfloat162float(h));
    }
}

// w[co][ci][3][3] fp32 -> buf[tap][co_off+co][ci] bf16 hi/lo (cout_buf-wide buffer)
__global__ void wsplit_kernel(const float* __restrict__ w, __nv_bfloat16* __restrict__ hi,
                              __nv_bfloat16* __restrict__ lo, int cout, int cin,
                              int co_off, int cout_buf)
{
    int i = blockIdx.x * 256 + threadIdx.x;
    int tot = 9 * cout * cin;
    if (i >= tot) return;
    int ci = i % cin; int r = i / cin; int co = r % cout; int tap = r / cout;
    float v = w[((size_t)co * cin + ci) * 9 + tap];
    __nv_bfloat16 h = __float2bfloat16(v);
    size_t o = ((size_t)tap * cout_buf + co_off + co) * cin + ci;
    hi[o] = h;
    lo[o] = __float2bfloat16(v - __bfloat162float(h));
}

__global__ void biascat_kernel(const float* __restrict__ b0, const float* __restrict__ b1,
                               float* __restrict__ dst)
{
    int i = threadIdx.x + blockIdx.x * 256;
    if (i < 288) dst[i] = i < 192 ? b0[i] : b1[i - 192];
}

// ---------------- tensor-core implicit-GEMM 3x3 conv ----------------
// CTA: M=128 pixels (2 rows) x NTILE couts (128 or 96, exact -> no N padding).
template<int CIN, int NTILE, bool TMAJOR>
__global__ void __launch_bounds__(256, 2)
conv_mma(const __nv_bfloat16* __restrict__ in_hi, const __nv_bfloat16* __restrict__ in_lo,
         const __nv_bfloat16* __restrict__ wt_hi, const __nv_bfloat16* __restrict__ wt_lo,
         const float* __restrict__ bias, float* __restrict__ out, int cout_total)
{
    extern __shared__ unsigned char smem_raw[];
    const unsigned sm_base = (unsigned)__cvta_generic_to_shared(smem_raw);
    const unsigned sA  = sm_base;                     // A hi then lo
    const unsigned sBb = sm_base + 2 * A_HALF_B;      // 3 slots x (hi,lo)

    const int tid = threadIdx.x;
    const int lane = tid & 31, warp = tid >> 5;
    const int gid = lane >> 2, tig = lane & 3;        // epilogue fragment coords
    const int jj = lane >> 3, rr = lane & 7;          // ldmatrix lane coords
    const int warpM = warp & 3, warpN = warp >> 2;

    constexpr int NA = NTILE / 16;                    // n-frags per row of accs (8 or 6)
    constexpr int NWARP = NTILE / 2;                  // n span per warp (64 or 48)

    const int Mbase = blockIdx.x * 128;
    const int Nbase = blockIdx.y * NTILE;
    const int img   = blockIdx.z;
    const int y0    = blockIdx.x * 2;

    const int NTAP_TOT = (CIN / 32) * 9;

    float acc[2][NA][4];
    #pragma unroll
    for (int ma = 0; ma < 2; ma++)
        #pragma unroll
        for (int na = 0; na < NA; na++)
            #pragma unroll
            for (int q = 0; q < 4; q++) acc[ma][na][q] = 0.f;

    // issue B slab for global tap g into slot g%3, always commit (group counting)
    auto issue_b = [&](int g) {
        if (g < NTAP_TOT) {
            int cbb = (g / 9) * 32;
            int tp  = g % 9;
            int slot = g % 3;
            #pragma unroll 1
            for (int i = tid; i < NTILE * 4; i += 256) {
                int n = i >> 2, seg = i & 3;
                size_t gsrc = ((size_t)(tp * cout_total + Nbase + n)) * CIN + cbb + seg * 8;
                cp16(sBb + (unsigned)(((slot * 2 + 0) * 128 + n) * CPB_B + seg * 16), wt_hi + gsrc, 16);
                cp16(sBb + (unsigned)(((slot * 2 + 1) * 128 + n) * CPB_B + seg * 16), wt_lo + gsrc, 16);
            }
        }
        asm volatile("cp.async.commit_group;\n" ::);
    };

    issue_b(0);
    issue_b(1);

    int g = 0;
    #pragma unroll 1
    for (int cb = 0; cb < CIN; cb += 32) {
        __syncthreads();   // all reads of A (previous chunk) complete

        // ---- stage A halo via cp.async (zero-fill OOB) ----
        #pragma unroll 1
        for (int i = tid; i < A_POS * 8; i += 256) {
            int pos = i >> 3, sub = i & 7;
            int hf = sub >> 2, seg = sub & 3;
            int ry = pos / 66, col = pos % 66;
            int gy = y0 - 1 + ry, gx = col - 1;
            int ok = ((unsigned)gy < 64u && (unsigned)gx < 64u) ? 16 : 0;
            int gyc = gy < 0 ? 0 : (gy > 63 ? 63 : gy);
            int gxc = gx < 0 ? 0 : (gx > 63 ? 63 : gx);
            const __nv_bfloat16* src = (hf ? in_lo : in_hi)
                + ((size_t)(img * HW + gyc * 64 + gxc)) * CIN + cb + seg * 8;
            cp16(sA + (unsigned)(hf * A_HALF_B + pos * CPA_B + seg * 16), src, ok);
        }
        asm volatile("cp.async.commit_group;\n" ::);

        #pragma unroll 1
        for (int tap = 0; tap < 9; tap++, g++) {
            if (tap == 0) asm volatile("cp.async.wait_group 0;\n" ::);  // drain incl. A group
            else          asm volatile("cp.async.wait_group 1;\n" ::);  // B(g) ready
            __syncthreads();

            const int dy = tap / 3, dx = tap - dy * 3;
            const int slot = g % 3;
            const unsigned sBh = sBb + (unsigned)((slot * 2 + 0) * 128 * CPB_B);
            const unsigned sBl = sBb + (unsigned)((slot * 2 + 1) * 128 * CPB_B);

            #pragma unroll
            for (int ks = 0; ks < 2; ks++) {
                const int kb2 = ks * 32;
                unsigned ra_h[2][4], ra_l[2][4];
                #pragma unroll
                for (int ma = 0; ma < 2; ma++) {
                    int pixel = warpM * 32 + ma * 16 + ((jj & 1) << 3) + rr;
                    int yy = (pixel >> 6) + dy;
                    int xx = (pixel & 63) + dx;
                    unsigned aofs = (unsigned)((yy * 66 + xx) * CPA_B + kb2 + ((jj >> 1) << 4));
                    ldsm4(ra_h[ma], sA + aofs);
                    ldsm4(ra_l[ma], sA + A_HALF_B + aofs);
                }
                #pragma unroll
                for (int np = 0; np < NA / 2; np++) {
                    int n = warpN * NWARP + (np * 2 + (jj >> 1)) * 8 + rr;
                    unsigned bofs = (unsigned)(n * CPB_B + kb2 + ((jj & 1) << 4));
                    unsigned rbh[4], rbl[4];
                    ldsm4(rbh, sBh + bofs);
                    ldsm4(rbl, sBl + bofs);
                    #pragma unroll
                    for (int ma = 0; ma < 2; ma++) {
                        mma16816(acc[ma][np * 2],     ra_h[ma], rbh[0], rbh[1]);
                        mma16816(acc[ma][np * 2],     ra_h[ma], rbl[0], rbl[1]);
                        mma16816(acc[ma][np * 2],     ra_l[ma], rbh[0], rbh[1]);
                        mma16816(acc[ma][np * 2 + 1], ra_h[ma], rbh[2], rbh[3]);
                        mma16816(acc[ma][np * 2 + 1], ra_h[ma], rbl[2], rbl[3]);
                        mma16816(acc[ma][np * 2 + 1], ra_l[ma], rbh[2], rbh[3]);
                    }
                }
            }
            issue_b(g + 2);
        }
    }

    // ---- epilogue ----
    #pragma unroll
    for (int ma = 0; ma < 2; ma++) {
        int pix = Mbase + warpM * 32 + ma * 16 + gid;
        #pragma unroll
        for (int na = 0; na < NA; na++) {
            int co = Nbase + warpN * NWARP + na * 8 + tig * 2;
            float bv0 = bias[co], bv1 = bias[co + 1];
            if (TMAJOR) {
                float2* p0 = reinterpret_cast<float2*>(out + ((size_t)img * HW + pix) * cout_total + co);
                float2* p1 = reinterpret_cast<float2*>(out + ((size_t)img * HW + pix + 8) * cout_total + co);
                *p0 = make_float2(acc[ma][na][0] + bv0, acc[ma][na][1] + bv1);
                *p1 = make_float2(acc[ma][na][2] + bv0, acc[ma][na][3] + bv1);
            } else {
                out[((size_t)img * cout_total + co)     * HW + pix]     = acc[ma][na][0] + bv0;
                out[((size_t)img * cout_total + co + 1) * HW + pix]     = acc[ma][na][1] + bv1;
                out[((size_t)img * cout_total + co)     * HW + pix + 8] = acc[ma][na][2] + bv0;
                out[((size_t)img * cout_total + co + 1) * HW + pix + 8] = acc[ma][na][3] + bv1;
            }
        }
    }
}

// ---------------- MSDA sampling + fused softmax; writes bf16 hi/lo -----------------
// oa_t: token-major [tok][288]: cols 0..191 = offsets, 192..287 = attn logits.
__global__ __launch_bounds__(256)
void msda_kernel(const float* __restrict__ value_t, const float* __restrict__ oa_t,
                 const float* __restrict__ refp,
                 __nv_bfloat16* __restrict__ out_hi, __nv_bfloat16* __restrict__ out_lo)
{
    int gw = blockIdx.x * 8 + (threadIdx.x >> 5);
    int lane = threadIdx.x & 31;
    int head = gw & 7;
    int pix  = (gw >> 3) & 4095;
    int b    = gw >> 15;

    size_t tok = (size_t)b * HW + pix;
    const float* op = oa_t + tok * 288;
    const float* ap = op + 192 + head * 12;

    float lg[12]; float mx = -1e30f;
    #pragma unroll
    for (int j = 0; j < 12; j++) { lg[j] = ap[j]; mx = fmaxf(mx, lg[j]); }
    float den = 0.f;
    #pragma unroll
    for (int j = 0; j < 12; j++) { lg[j] = expf(lg[j] - mx); den += lg[j]; }
    float rden = 1.f / den;

    float acc = 0.f;
    #pragma unroll
    for (int l = 0; l < 3; l++) {
        float rx = refp[(tok * 3 + l) * 2 + 0];
        float ry = refp[(tok * 3 + l) * 2 + 1];
        const float* vb = value_t + ((size_t)(b * 3 + l) * HW) * 256 + head * 32 + lane;
        #pragma unroll
        for (int p = 0; p < 4; p++) {
            int ch = ((head * 3 + l) * 4 + p) * 2;
            float ox = op[ch], oy = op[ch + 1];
            float a = lg[l * 4 + p] * rden;
            float xf = rx * 64.f + ox - 0.5f;
            float yf = ry * 64.f + oy - 0.5f;
            float x0f = floorf(xf), y0f = floorf(yf);
            int x0 = (int)x0f, y0 = (int)y0f;
            float lx = xf - x0f, ly = yf - y0f;
            float w00 = (1.f - lx) * (1.f - ly) * a;
            float w10 = lx * (1.f - ly) * a;
            float w01 = (1.f - lx) * ly * a;
            float w11 = lx * ly * a;
            if ((unsigned)x0       < 64u && (unsigned)y0       < 64u) acc += w00 * vb[(size_t)(y0 * 64 + x0) * 256];
            if ((unsigned)(x0 + 1) < 64u && (unsigned)y0       < 64u) acc += w10 * vb[(size_t)(y0 * 64 + x0 + 1) * 256];
            if ((unsigned)x0       < 64u && (unsigned)(y0 + 1) < 64u) acc += w01 * vb[(size_t)((y0 + 1) * 64 + x0) * 256];
            if ((unsigned)(x0 + 1) < 64u && (unsigned)(y0 + 1) < 64u) acc += w11 * vb[(size_t)((y0 + 1) * 64 + x0 + 1) * 256];
        }
    }
    __nv_bfloat16 h = __float2bfloat16(acc);
    size_t o = tok * 256 + head * 32 + lane;
    out_hi[o] = h;
    out_lo[o] = __float2bfloat16(acc - __bfloat162float(h));
}

// ---------------- launcher ----------------------------------------------------------
extern "C" void kernel_launch(void* const* d_in, const int* in_sizes, int n_in,
                              void* d_out, int out_size)
{
    const float* query   = (const float*)d_in[0];
    const float* refp    = (const float*)d_in[1];
    const float* flat    = (const float*)d_in[2];
    const float* w_value = (const float*)d_in[6];
    const float* b_value = (const float*)d_in[7];
    const float* w_off   = (const float*)d_in[8];
    const float* b_off   = (const float*)d_in[9];
    const float* w_attn  = (const float*)d_in[10];
    const float* b_attn  = (const float*)d_in[11];
    const float* w_out   = (const float*)d_in[12];
    const float* b_out   = (const float*)d_in[13];

    __nv_bfloat16 *q_hi, *q_lo, *f_hi, *f_lo, *s_hi, *s_lo;
    __nv_bfloat16 *wv_hi, *wv_lo, *woa_hi, *woa_lo, *wu_hi, *wu_lo;
    float *value_t, *oa_t, *boa;
    cudaGetSymbolAddress((void**)&q_hi, g_q_hi);   cudaGetSymbolAddress((void**)&q_lo, g_q_lo);
    cudaGetSymbolAddress((void**)&f_hi, g_flat_hi);cudaGetSymbolAddress((void**)&f_lo, g_flat_lo);
    cudaGetSymbolAddress((void**)&s_hi, g_samp_hi);cudaGetSymbolAddress((void**)&s_lo, g_samp_lo);
    cudaGetSymbolAddress((void**)&wv_hi, g_wv_hi); cudaGetSymbolAddress((void**)&wv_lo, g_wv_lo);
    cudaGetSymbolAddress((void**)&woa_hi, g_woa_hi); cudaGetSymbolAddress((void**)&woa_lo, g_woa_lo);
    cudaGetSymbolAddress((void**)&wu_hi, g_wu_hi); cudaGetSymbolAddress((void**)&wu_lo, g_wu_lo);
    cudaGetSymbolAddress((void**)&value_t, g_value_t);
    cudaGetSymbolAddress((void**)&oa_t,    g_oa_t);
    cudaGetSymbolAddress((void**)&boa,     g_boa);

    cudaFuncSetAttribute(conv_mma<256, 128, true>,  cudaFuncAttributeMaxDynamicSharedMemorySize, SMEM_BYTES);
    cudaFuncSetAttribute(conv_mma<768, 96,  true>,  cudaFuncAttributeMaxDynamicSharedMemorySize, SMEM_BYTES);
    cudaFuncSetAttribute(conv_mma<256, 128, false>, cudaFuncAttributeMaxDynamicSharedMemorySize, SMEM_BYTES);

    // launch 0..2: prerequisites of the value conv
    chlast_split<<<dim3(128, 8, 12), dim3(32, 8)>>>(flat, f_hi, f_lo, 256);
    wsplit_kernel<<<(9 * 256 * 256 + 255) / 256, 256>>>(w_value, wv_hi, wv_lo, 256, 256, 0, 256);
    chlast_split<<<dim3(128, 24, 4), dim3(32, 8)>>>(query, q_hi, q_lo, 768);

    // launch 3: value conv (ncu profiling window)
    conv_mma<256, 128, true><<<dim3(32, 2, 12), 256, SMEM_BYTES>>>(f_hi, f_lo, wv_hi, wv_lo, b_value, value_t, 256);

    // merged off+attn weights/bias
    wsplit_kernel<<<(9 * 192 * 768 + 255) / 256, 256>>>(w_off,  woa_hi, woa_lo, 192, 768, 0,   288);
    wsplit_kernel<<<(9 * 96  * 768 + 255) / 256, 256>>>(w_attn, woa_hi, woa_lo, 96,  768, 192, 288);
    biascat_kernel<<<2, 256>>>(b_off, b_attn, boa);
    wsplit_kernel<<<(9 * 256 * 256 + 255) / 256, 256>>>(w_out, wu_hi, wu_lo, 256, 256, 0, 256);

    // merged off+attn conv: cout=288, NTILE=96 -> zero padding, 384 uniform CTAs
    conv_mma<768, 96, true><<<dim3(32, 3, 4), 256, SMEM_BYTES>>>(q_hi, q_lo, woa_hi, woa_lo, boa, oa_t, 288);

    msda_kernel<<<(4 * HW * 8) / 8, 256>>>(value_t, oa_t, refp, s_hi, s_lo);

    conv_mma<256, 128, false><<<dim3(32, 2, 4), 256, SMEM_BYTES>>>(s_hi, s_lo, wu_hi, wu_lo, b_out, (float*)d_out, 256);
}

// round 7
// speedup vs baseline: 4.8653x; 1.1287x over previous
#include <cuda_runtime.h>
#include <cuda_bf16.h>
#include <cstdint>
#include <math.h>

#define HW 4096
#define CPA_B 80                    // A smem row stride (bytes), 16B-aligned for ldmatrix
#define CPB_B 80                    // B smem row stride (bytes)
#define A_POS (4 * 66)              // halo positions per chunk tile
#define A_HALF_B (A_POS * CPA_B)    // bytes per hi/lo half
#define B_SLOT_B (2 * 128 * CPB_B)  // slot sized for 128 rows (96 uses a subset)
#define SMEM_BYTES (2 * A_HALF_B + 3 * B_SLOT_B)   // 103680

// ---------------- device scratch ----------------
__device__ __nv_bfloat16 g_q_hi   [4u * 4096u * 768u];
__device__ __nv_bfloat16 g_q_lo   [4u * 4096u * 768u];
__device__ __nv_bfloat16 g_flat_hi[12u * 4096u * 256u];
__device__ __nv_bfloat16 g_flat_lo[12u * 4096u * 256u];
__device__ __nv_bfloat16 g_samp_hi[4u * 4096u * 256u];
__device__ __nv_bfloat16 g_samp_lo[4u * 4096u * 256u];
__device__ float g_value_t[12u * 4096u * 256u];
__device__ float g_oa_t   [4u * 4096u * 288u];        // merged off(0:192)+attn(192:288), token-major
__device__ float g_boa    [288];
__device__ __nv_bfloat16 g_wv_hi [9u * 256u * 256u], g_wv_lo [9u * 256u * 256u];
__device__ __nv_bfloat16 g_woa_hi[9u * 288u * 768u], g_woa_lo[9u * 288u * 768u];
__device__ __nv_bfloat16 g_wu_hi [9u * 256u * 256u], g_wu_lo [9u * 256u * 256u];

// ---------------- helpers ----------------
__device__ __forceinline__ void mma16816(float* c, const unsigned* a, unsigned b0, unsigned b1)
{
    asm volatile("mma.sync.aligned.m16n8k16.row.col.f32.bf16.bf16.f32 "
        "{%0,%1,%2,%3}, {%4,%5,%6,%7}, {%8,%9}, {%0,%1,%2,%3};"
        : "+f"(c[0]), "+f"(c[1]), "+f"(c[2]), "+f"(c[3])
        : "r"(a[0]), "r"(a[1]), "r"(a[2]), "r"(a[3]), "r"(b0), "r"(b1));
}

__device__ __forceinline__ void cp16(unsigned daddr, const void* src, int srcsz)
{
    asm volatile("cp.async.cg.shared.global [%0], [%1], 16, %2;\n"
                 :: "r"(daddr), "l"(src), "r"(srcsz));
}

__device__ __forceinline__ void ldsm4(unsigned* d, unsigned saddr)
{
    asm volatile("ldmatrix.sync.aligned.m8n8.x4.shared.b16 {%0,%1,%2,%3}, [%4];"
        : "=r"(d[0]), "=r"(d[1]), "=r"(d[2]), "=r"(d[3]) : "r"(saddr));
}

// ---------------- conversion kernels ----------------
__global__ void chlast_split(const float* __restrict__ in, __nv_bfloat16* __restrict__ hi,
                             __nv_bfloat16* __restrict__ lo, int C)
{
    __shared__ float t[32][33];
    int img = blockIdx.z;
    int p0 = blockIdx.x * 32, c0 = blockIdx.y * 32;
    int tx = threadIdx.x;
    for (int j = threadIdx.y; j < 32; j += 8)
        t[j][tx] = in[((size_t)img * C + c0 + j) * HW + p0 + tx];
    __syncthreads();
    for (int j = threadIdx.y; j < 32; j += 8) {
        float v = t[tx][j];
        __nv_bfloat16 h = __float2bfloat16(v);
        size_t o = ((size_t)img * HW + p0 + j) * C + c0 + tx;
        hi[o] = h;
        lo[o] = __float2bfloat16(v - __bfloat162float(h));
    }
}

// put one weight element: w[co][ci][3][3] -> buf[tap][co_off+co][ci]
__device__ __forceinline__ void wput(const float* __restrict__ w, __nv_bfloat16* hi,
                                     __nv_bfloat16* lo, int i, int cout, int cin,
                                     int co_off, int cout_buf)
{
    int ci = i % cin; int r = i / cin; int co = r % cout; int tap = r / cout;
    float v = w[((size_t)co * cin + ci) * 9 + tap];
    __nv_bfloat16 h = __float2bfloat16(v);
    size_t o = ((size_t)tap * cout_buf + co_off + co) * cin + ci;
    hi[o] = h;
    lo[o] = __float2bfloat16(v - __bfloat162float(h));
}

// all weight conversions + bias concat in ONE launch (keeps conv_pair at launch idx 3)
#define WN0 (9 * 256 * 256)
#define WN1 (9 * 192 * 768)
#define WN2 (9 * 96  * 768)
#define WN3 (9 * 256 * 256)
__global__ void wprep(const float* __restrict__ wv, const float* __restrict__ wo,
                      const float* __restrict__ wa, const float* __restrict__ wu,
                      const float* __restrict__ bo, const float* __restrict__ ba)
{
    int i = blockIdx.x * 256 + threadIdx.x;
    if (i < WN0) {
        wput(wv, g_wv_hi, g_wv_lo, i, 256, 256, 0, 256);
    } else if (i < WN0 + WN1) {
        wput(wo, g_woa_hi, g_woa_lo, i - WN0, 192, 768, 0, 288);
    } else if (i < WN0 + WN1 + WN2) {
        wput(wa, g_woa_hi, g_woa_lo, i - WN0 - WN1, 96, 768, 192, 288);
    } else if (i < WN0 + WN1 + WN2 + WN3) {
        wput(wu, g_wu_hi, g_wu_lo, i - WN0 - WN1 - WN2, 256, 256, 0, 256);
    } else if (i < WN0 + WN1 + WN2 + WN3 + 288) {
        int j = i - (WN0 + WN1 + WN2 + WN3);
        g_boa[j] = j < 192 ? bo[j] : ba[j - 192];
    }
}

// ---------------- tensor-core implicit-GEMM 3x3 conv body ----------------
// M=128 pixels (2 rows) x NTILE couts (128 or 96, exact -> no N padding).
template<int CIN, int NTILE, bool TMAJOR>
__device__ __forceinline__ void conv_body(
         int bx, int by, int img,
         const __nv_bfloat16* __restrict__ in_hi, const __nv_bfloat16* __restrict__ in_lo,
         const __nv_bfloat16* __restrict__ wt_hi, const __nv_bfloat16* __restrict__ wt_lo,
         const float* __restrict__ bias, float* __restrict__ out, int cout_total)
{
    extern __shared__ unsigned char smem_raw[];
    const unsigned sm_base = (unsigned)__cvta_generic_to_shared(smem_raw);
    const unsigned sA  = sm_base;                     // A hi then lo
    const unsigned sBb = sm_base + 2 * A_HALF_B;      // 3 slots x (hi,lo)

    const int tid = threadIdx.x;
    const int lane = tid & 31, warp = tid >> 5;
    const int gid = lane >> 2, tig = lane & 3;        // epilogue fragment coords
    const int jj = lane >> 3, rr = lane & 7;          // ldmatrix lane coords
    const int warpM = warp & 3, warpN = warp >> 2;

    constexpr int NA = NTILE / 16;                    // n-frags (8 or 6)
    constexpr int NWARP = NTILE / 2;                  // n span per warp (64 or 48)

    const int Mbase = bx * 128;
    const int Nbase = by * NTILE;
    const int y0    = bx * 2;

    const int NTAP_TOT = (CIN / 32) * 9;

    float acc[2][NA][4];
    #pragma unroll
    for (int ma = 0; ma < 2; ma++)
        #pragma unroll
        for (int na = 0; na < NA; na++)
            #pragma unroll
            for (int q = 0; q < 4; q++) acc[ma][na][q] = 0.f;

    // issue B slab for global tap g into slot g%3, always commit (group counting)
    auto issue_b = [&](int g) {
        if (g < NTAP_TOT) {
            int cbb = (g / 9) * 32;
            int tp  = g % 9;
            int slot = g % 3;
            #pragma unroll 1
            for (int i = tid; i < NTILE * 4; i += 256) {
                int n = i >> 2, seg = i & 3;
                size_t gsrc = ((size_t)(tp * cout_total + Nbase + n)) * CIN + cbb + seg * 8;
                cp16(sBb + (unsigned)(((slot * 2 + 0) * 128 + n) * CPB_B + seg * 16), wt_hi + gsrc, 16);
                cp16(sBb + (unsigned)(((slot * 2 + 1) * 128 + n) * CPB_B + seg * 16), wt_lo + gsrc, 16);
            }
        }
        asm volatile("cp.async.commit_group;\n" ::);
    };

    issue_b(0);
    issue_b(1);

    int g = 0;
    #pragma unroll 1
    for (int cb = 0; cb < CIN; cb += 32) {
        __syncthreads();   // all reads of A (previous chunk) complete

        // ---- stage A halo via cp.async (zero-fill OOB) ----
        #pragma unroll 1
        for (int i = tid; i < A_POS * 8; i += 256) {
            int pos = i >> 3, sub = i & 7;
            int hf = sub >> 2, seg = sub & 3;
            int ry = pos / 66, col = pos % 66;
            int gy = y0 - 1 + ry, gx = col - 1;
            int ok = ((unsigned)gy < 64u && (unsigned)gx < 64u) ? 16 : 0;
            int gyc = gy < 0 ? 0 : (gy > 63 ? 63 : gy);
            int gxc = gx < 0 ? 0 : (gx > 63 ? 63 : gx);
            const __nv_bfloat16* src = (hf ? in_lo : in_hi)
                + ((size_t)(img * HW + gyc * 64 + gxc)) * CIN + cb + seg * 8;
            cp16(sA + (unsigned)(hf * A_HALF_B + pos * CPA_B + seg * 16), src, ok);
        }
        asm volatile("cp.async.commit_group;\n" ::);

        #pragma unroll 1
        for (int tap = 0; tap < 9; tap++, g++) {
            if (tap == 0) asm volatile("cp.async.wait_group 0;\n" ::);  // drain incl. A group
            else          asm volatile("cp.async.wait_group 1;\n" ::);  // B(g) ready
            __syncthreads();

            const int dy = tap / 3, dx = tap - dy * 3;
            const int slot = g % 3;
            const unsigned sBh = sBb + (unsigned)((slot * 2 + 0) * 128 * CPB_B);
            const unsigned sBl = sBb + (unsigned)((slot * 2 + 1) * 128 * CPB_B);

            #pragma unroll
            for (int ks = 0; ks < 2; ks++) {
                const int kb2 = ks * 32;
                unsigned ra_h[2][4], ra_l[2][4];
                #pragma unroll
                for (int ma = 0; ma < 2; ma++) {
                    int pixel = warpM * 32 + ma * 16 + ((jj & 1) << 3) + rr;
                    int yy = (pixel >> 6) + dy;
                    int xx = (pixel & 63) + dx;
                    unsigned aofs = (unsigned)((yy * 66 + xx) * CPA_B + kb2 + ((jj >> 1) << 4));
                    ldsm4(ra_h[ma], sA + aofs);
                    ldsm4(ra_l[ma], sA + A_HALF_B + aofs);
                }
                #pragma unroll
                for (int np = 0; np < NA / 2; np++) {
                    int n = warpN * NWARP + (np * 2 + (jj >> 1)) * 8 + rr;
                    unsigned bofs = (unsigned)(n * CPB_B + kb2 + ((jj & 1) << 4));
                    unsigned rbh[4], rbl[4];
                    ldsm4(rbh, sBh + bofs);
                    ldsm4(rbl, sBl + bofs);
                    #pragma unroll
                    for (int ma = 0; ma < 2; ma++) {
                        mma16816(acc[ma][np * 2],     ra_h[ma], rbh[0], rbh[1]);
                        mma16816(acc[ma][np * 2],     ra_h[ma], rbl[0], rbl[1]);
                        mma16816(acc[ma][np * 2],     ra_l[ma], rbh[0], rbh[1]);
                        mma16816(acc[ma][np * 2 + 1], ra_h[ma], rbh[2], rbh[3]);
                        mma16816(acc[ma][np * 2 + 1], ra_h[ma], rbl[2], rbl[3]);
                        mma16816(acc[ma][np * 2 + 1], ra_l[ma], rbh[2], rbh[3]);
                    }
                }
            }
            issue_b(g + 2);
        }
    }

    // ---- epilogue ----
    #pragma unroll
    for (int ma = 0; ma < 2; ma++) {
        int pix = Mbase + warpM * 32 + ma * 16 + gid;
        #pragma unroll
        for (int na = 0; na < NA; na++) {
            int co = Nbase + warpN * NWARP + na * 8 + tig * 2;
            float bv0 = bias[co], bv1 = bias[co + 1];
            if (TMAJOR) {
                float2* p0 = reinterpret_cast<float2*>(out + ((size_t)img * HW + pix) * cout_total + co);
                float2* p1 = reinterpret_cast<float2*>(out + ((size_t)img * HW + pix + 8) * cout_total + co);
                *p0 = make_float2(acc[ma][na][0] + bv0, acc[ma][na][1] + bv1);
                *p1 = make_float2(acc[ma][na][2] + bv0, acc[ma][na][3] + bv1);
            } else {
                out[((size_t)img * cout_total + co)     * HW + pix]     = acc[ma][na][0] + bv0;
                out[((size_t)img * cout_total + co + 1) * HW + pix]     = acc[ma][na][1] + bv1;
                out[((size_t)img * cout_total + co)     * HW + pix + 8] = acc[ma][na][2] + bv0;
                out[((size_t)img * cout_total + co + 1) * HW + pix + 8] = acc[ma][na][3] + bv1;
            }
        }
    }
}

// ---- merged launch: oa conv (384 long CTAs) first, then value conv (768 short) ----
__global__ void __launch_bounds__(256, 2)
conv_pair(const float* __restrict__ b_value)
{
    int bxg = blockIdx.x;
    if (bxg < 384) {
        int x = bxg & 31, y = (bxg >> 5) % 3, img = bxg / 96;
        conv_body<768, 96, true>(x, y, img, g_q_hi, g_q_lo, g_woa_hi, g_woa_lo,
                                 g_boa, g_oa_t, 288);
    } else {
        int t = bxg - 384;
        int x = t & 31, y = (t >> 5) & 1, img = t >> 6;
        conv_body<256, 128, true>(x, y, img, g_flat_hi, g_flat_lo, g_wv_hi, g_wv_lo,
                                  b_value, g_value_t, 256);
    }
}

// ---- out conv (depends on msda) ----
__global__ void __launch_bounds__(256, 2)
conv_out(const float* __restrict__ b_out, float* __restrict__ out)
{
    conv_body<256, 128, false>(blockIdx.x, blockIdx.y, blockIdx.z,
                               g_samp_hi, g_samp_lo, g_wu_hi, g_wu_lo, b_out, out, 256);
}

// ---------------- MSDA sampling + fused softmax; writes bf16 hi/lo -----------------
__global__ __launch_bounds__(256)
void msda_kernel(const float* __restrict__ refp)
{
    int gw = blockIdx.x * 8 + (threadIdx.x >> 5);
    int lane = threadIdx.x & 31;
    int head = gw & 7;
    int pix  = (gw >> 3) & 4095;
    int b    = gw >> 15;

    size_t tok = (size_t)b * HW + pix;
    const float* op = g_oa_t + tok * 288;
    const float* ap = op + 192 + head * 12;

    float lg[12]; float mx = -1e30f;
    #pragma unroll
    for (int j = 0; j < 12; j++) { lg[j] = ap[j]; mx = fmaxf(mx, lg[j]); }
    float den = 0.f;
    #pragma unroll
    for (int j = 0; j < 12; j++) { lg[j] = expf(lg[j] - mx); den += lg[j]; }
    float rden = 1.f / den;

    float acc = 0.f;
    #pragma unroll
    for (int l = 0; l < 3; l++) {
        float rx = refp[(tok * 3 + l) * 2 + 0];
        float ry = refp[(tok * 3 + l) * 2 + 1];
        const float* vb = g_value_t + ((size_t)(b * 3 + l) * HW) * 256 + head * 32 + lane;
        #pragma unroll
        for (int p = 0; p < 4; p++) {
            int ch = ((head * 3 + l) * 4 + p) * 2;
            float ox = op[ch], oy = op[ch + 1];
            float a = lg[l * 4 + p] * rden;
            float xf = rx * 64.f + ox - 0.5f;
            float yf = ry * 64.f + oy - 0.5f;
            float x0f = floorf(xf), y0f = floorf(yf);
            int x0 = (int)x0f, y0 = (int)y0f;
            float lx = xf - x0f, ly = yf - y0f;
            float w00 = (1.f - lx) * (1.f - ly) * a;
            float w10 = lx * (1.f - ly) * a;
            float w01 = (1.f - lx) * ly * a;
            float w11 = lx * ly * a;
            if ((unsigned)x0       < 64u && (unsigned)y0       < 64u) acc += w00 * vb[(size_t)(y0 * 64 + x0) * 256];
            if ((unsigned)(x0 + 1) < 64u && (unsigned)y0       < 64u) acc += w10 * vb[(size_t)(y0 * 64 + x0 + 1) * 256];
            if ((unsigned)x0       < 64u && (unsigned)(y0 + 1) < 64u) acc += w01 * vb[(size_t)((y0 + 1) * 64 + x0) * 256];
            if ((unsigned)(x0 + 1) < 64u && (unsigned)(y0 + 1) < 64u) acc += w11 * vb[(size_t)((y0 + 1) * 64 + x0 + 1) * 256];
        }
    }
    __nv_bfloat16 h = __float2bfloat16(acc);
    size_t o = tok * 256 + head * 32 + lane;
    g_samp_hi[o] = h;
    g_samp_lo[o] = __float2bfloat16(acc - __bfloat162float(h));
}

// ---------------- launcher ----------------------------------------------------------
extern "C" void kernel_launch(void* const* d_in, const int* in_sizes, int n_in,
                              void* d_out, int out_size)
{
    const float* query   = (const float*)d_in[0];
    const float* refp    = (const float*)d_in[1];
    const float* flat    = (const float*)d_in[2];
    const float* w_value = (const float*)d_in[6];
    const float* b_value = (const float*)d_in[7];
    const float* w_off   = (const float*)d_in[8];
    const float* b_off   = (const float*)d_in[9];
    const float* w_attn  = (const float*)d_in[10];
    const float* b_attn  = (const float*)d_in[11];
    const float* w_out   = (const float*)d_in[12];
    const float* b_out   = (const float*)d_in[13];

    __nv_bfloat16 *q_hi, *q_lo, *f_hi, *f_lo;
    cudaGetSymbolAddress((void**)&q_hi, g_q_hi);
    cudaGetSymbolAddress((void**)&q_lo, g_q_lo);
    cudaGetSymbolAddress((void**)&f_hi, g_flat_hi);
    cudaGetSymbolAddress((void**)&f_lo, g_flat_lo);

    cudaFuncSetAttribute(conv_pair, cudaFuncAttributeMaxDynamicSharedMemorySize, SMEM_BYTES);
    cudaFuncSetAttribute(conv_out,  cudaFuncAttributeMaxDynamicSharedMemorySize, SMEM_BYTES);

    // launch 0..2: input conversions + all weight prep (fused)
    chlast_split<<<dim3(128, 8, 12), dim3(32, 8)>>>(flat, f_hi, f_lo, 256);
    chlast_split<<<dim3(128, 24, 4), dim3(32, 8)>>>(query, q_hi, q_lo, 768);
    wprep<<<(WN0 + WN1 + WN2 + WN3 + 288 + 255) / 256, 256>>>(w_value, w_off, w_attn, w_out, b_off, b_attn);

    // launch 3 (ncu window): merged value + off/attn convs, long CTAs first
    conv_pair<<<1152, 256, SMEM_BYTES>>>(b_value);

    // launch 4: deformable attention sampling
    msda_kernel<<<(4 * HW * 8) / 8, 256>>>(refp);

    // launch 5: output conv -> NCHW d_out
    conv_out<<<dim3(32, 2, 4), 256, SMEM_BYTES>>>(b_out, (float*)d_out);
}